// round 6
// baseline (speedup 1.0000x reference)
#include <cuda_runtime.h>
#include <cstdint>
#include <math.h>

#define TOKENS 16384
#define DIM    2048
#define NEXP   8
#define RANK   16
#define NFEAT  128
#define KC     32
#define NIT    (DIM/KC)      // 64
#define PAD1   36
#define PAD2   132
#define SA_STAGE (128*PAD1)  // 4608 floats

// -------- device scratch --------
__device__ float g_mask[TOKENS*NEXP];
__device__ float g_B2[DIM*NFEAT];     // pre-rounded tf32, pair-permuted along feat
__device__ float g_W1c[NFEAT*DIM];    // pre-rounded tf32, pair-permuted along K
__device__ float g_probs_fallback[TOKENS*NEXP];

// -------- helpers --------
__device__ __forceinline__ uint32_t f2tf(float f){
    uint32_t u; asm("cvt.rna.tf32.f32 %0, %1;" : "=r"(u) : "f"(f)); return u;
}
__device__ __forceinline__ float rndtf(float f){ return __uint_as_float(f2tf(f)); }
__device__ __forceinline__ void mma8(float c[4], const uint32_t a[4], const uint32_t b[2]){
    asm volatile(
      "mma.sync.aligned.m16n8k8.row.col.f32.tf32.tf32.f32 "
      "{%0,%1,%2,%3},{%4,%5,%6,%7},{%8,%9},{%0,%1,%2,%3};"
      : "+f"(c[0]), "+f"(c[1]), "+f"(c[2]), "+f"(c[3])
      : "r"(a[0]), "r"(a[1]), "r"(a[2]), "r"(a[3]), "r"(b[0]), "r"(b[1]));
}
__device__ __forceinline__ void cp16(void* s, const void* g){
    uint32_t sa = (uint32_t)__cvta_generic_to_shared(s);
    asm volatile("cp.async.cg.shared.global [%0], [%1], 16;" :: "r"(sa), "l"(g));
}
__device__ __forceinline__ void cp_commit(){ asm volatile("cp.async.commit_group;"); }
template<int N> __device__ __forceinline__ void cp_wait(){
    asm volatile("cp.async.wait_group %0;" :: "n"(N));
}
__device__ __forceinline__ float gelu_exact(float v){
    return 0.5f * v * (1.0f + erff(v * 0.70710678118654752f));
}
// pair-permute within 8-group: pairs (i, i+4) become adjacent
__host__ __device__ __forceinline__ int perm8(int i){
    return ((i & 3) << 1) | ((i >> 2) & 1);
}

// ================= Kernel 1: gate (fp32 exact) =================
// 512 thr, 4 tokens/warp -> 64 tokens/CTA, grid 256. W staged in SMEM.
__global__ __launch_bounds__(512) void gate_kernel(
    const float* __restrict__ x, const float* __restrict__ W,
    const float* __restrict__ bias, float* __restrict__ probs)
{
    extern __shared__ float Wsm[];           // 8*2048 floats = 64KB
    {
        const float4* Wg = reinterpret_cast<const float4*>(W);
        float4* Ws4 = reinterpret_cast<float4*>(Wsm);
        #pragma unroll
        for (int i = threadIdx.x; i < NEXP*DIM/4; i += 512) Ws4[i] = Wg[i];
    }
    __syncthreads();

    int warp = threadIdx.x >> 5, lane = threadIdx.x & 31;
    int tok0 = (blockIdx.x * 16 + warp) * 4;
    const float4* x4 = reinterpret_cast<const float4*>(x);
    const float4* W4 = reinterpret_cast<const float4*>(Wsm);

    float acc[4][8];
    #pragma unroll
    for (int t = 0; t < 4; t++)
        #pragma unroll
        for (int e = 0; e < 8; e++) acc[t][e] = 0.f;

    #pragma unroll 2
    for (int i = lane; i < 512; i += 32){
        float4 xv[4];
        #pragma unroll
        for (int t = 0; t < 4; t++) xv[t] = x4[(size_t)(tok0 + t) * 512 + i];
        #pragma unroll
        for (int e = 0; e < 8; e++){
            float4 w = W4[e * 512 + i];
            #pragma unroll
            for (int t = 0; t < 4; t++)
                acc[t][e] += xv[t].x*w.x + xv[t].y*w.y + xv[t].z*w.z + xv[t].w*w.w;
        }
    }
    #pragma unroll
    for (int t = 0; t < 4; t++)
        #pragma unroll
        for (int e = 0; e < 8; e++){
            float v = acc[t][e];
            #pragma unroll
            for (int s = 16; s > 0; s >>= 1) v += __shfl_xor_sync(0xffffffffu, v, s);
            acc[t][e] = v;
        }
    if (lane < 4){
        int t = lane;
        int tok = tok0 + t;
        float lg[8]; float mx = -1e30f;
        #pragma unroll
        for (int e = 0; e < 8; e++){ lg[e] = acc[t][e] + bias[e]; mx = fmaxf(mx, lg[e]); }
        float p[8]; float s = 0.f;
        #pragma unroll
        for (int e = 0; e < 8; e++){ p[e] = expf(lg[e] - mx); s += p[e]; }
        float inv = 1.f / s;
        #pragma unroll
        for (int e = 0; e < 8; e++) probs[tok*8 + e] = p[e] * inv;
        int i1 = 0;
        #pragma unroll
        for (int e = 1; e < 8; e++) if (lg[e] > lg[i1]) i1 = e;
        int i2 = (i1 == 0) ? 1 : 0;
        #pragma unroll
        for (int e = 0; e < 8; e++) if (e != i1 && lg[e] > lg[i2]) i2 = e;
        #pragma unroll
        for (int e = 0; e < 8; e++)
            g_mask[tok*8 + e] = (e == i1 || e == i2) ? 1.0f : 0.0f;
    }
}

// ===== Kernel 2: pack + pre-round to tf32 + pair-permute =====
__global__ void pack_kernel(const float* __restrict__ Bm, const float* __restrict__ A){
    int t = blockIdx.x * blockDim.x + threadIdx.x;
    if (t < DIM * NFEAT){
        int d = t >> 7; int j = t & 127; int e = j >> 4; int r = j & 15;
        int jp = (j & ~7) | perm8(j & 7);
        g_B2[d * NFEAT + jp] = rndtf(Bm[e * (DIM * RANK) + d * RANK + r]);
    } else if (t < 2 * DIM * NFEAT){
        int u = t - DIM * NFEAT;        // u = row*2048 + k
        int k = u & (DIM - 1);
        int kp = (k & ~7) | perm8(k & 7);
        g_W1c[(u - k) + kp] = rndtf(A[u]);
    }
}

// ========= Kernel 3: fused GEMM1 -> gelu*mask -> GEMM2 =========
// 128 tokens/CTA, grid 128, 512 thr (16 warps, 4M x 4N).
__global__ __launch_bounds__(512) void fused_kernel(
    const float* __restrict__ x, float* __restrict__ out)
{
    extern __shared__ float sm[];
    float* Xs  = sm;                    // 3 stages * 4608
    float* Ws  = sm + 3 * SA_STAGE;     // 3 stages * 4608
    float* Hs  = sm + 6 * SA_STAGE;     // 128*132
    float* Bs2 = sm;                    // alias of X/W region (dead in phase 2)

    const int tid  = threadIdx.x;
    const int warp = tid >> 5, lane = tid & 31;
    const int g = lane >> 2, t4 = lane & 3;
    const int mw = warp & 3, nw = warp >> 2;
    const int tokBase = blockIdx.x * 128;

    // ---------------- GEMM1: H = X @ W1^T, K = 2048, 3-stage PF=2 ----------------
    float acc[2][4][4];
    #pragma unroll
    for (int mf = 0; mf < 2; mf++)
        #pragma unroll
        for (int nf = 0; nf < 4; nf++)
            #pragma unroll
            for (int k = 0; k < 4; k++) acc[mf][nf][k] = 0.f;

    auto copyXW = [&](int it){
        int st = (it % 3) * SA_STAGE;
        int kb = it * KC;
        #pragma unroll
        for (int i = 0; i < 2; i++){
            int q = tid + i*512; int row = q >> 3; int c4 = q & 7;
            cp16(&Xs[st + row*PAD1 + c4*4],
                 &x[(size_t)(tokBase + row) * DIM + kb + c4*4]);
        }
        #pragma unroll
        for (int i = 0; i < 2; i++){
            int q = tid + i*512; int row = q >> 3; int c4 = q & 7;
            cp16(&Ws[st + row*PAD1 + c4*4],
                 &g_W1c[(size_t)row * DIM + kb + c4*4]);
        }
    };

    copyXW(0); cp_commit();
    copyXW(1); cp_commit();

    for (int it = 0; it < NIT; ++it){
        // prefetch (distance 2); NO empty commits at the tail
        if (it + 2 < NIT){ copyXW(it + 2); cp_commit(); }
        // exact tail-aware wait: stage `it` group must be retired
        if      (it + 2 < NIT) cp_wait<2>();
        else if (it + 1 < NIT) cp_wait<1>();
        else                   cp_wait<0>();
        __syncthreads();   // publish ALL threads' copies of stage `it`

        const float* Ab = Xs + (it % 3) * SA_STAGE + mw*32*PAD1;
        const float* Wb = Ws + (it % 3) * SA_STAGE + nw*32*PAD1;
        #pragma unroll
        for (int ks = 0; ks < 4; ks++){
            int kc = ks * 8;
            uint32_t a[2][4];
            #pragma unroll
            for (int mf = 0; mf < 2; mf++){
                a[mf][0] = f2tf(Ab[(mf*16 +     g)*PAD1 + kc + t4]);
                a[mf][1] = f2tf(Ab[(mf*16 + 8 + g)*PAD1 + kc + t4]);
                a[mf][2] = f2tf(Ab[(mf*16 +     g)*PAD1 + kc + t4 + 4]);
                a[mf][3] = f2tf(Ab[(mf*16 + 8 + g)*PAD1 + kc + t4 + 4]);
            }
            #pragma unroll
            for (int nf = 0; nf < 4; nf++){
                float2 bv = *reinterpret_cast<const float2*>(
                    &Wb[(nf*8 + g)*PAD1 + kc + 2*t4]);   // permuted pair (t4, t4+4)
                uint32_t b[2] = { __float_as_uint(bv.x), __float_as_uint(bv.y) };
                #pragma unroll
                for (int mf = 0; mf < 2; mf++) mma8(acc[mf][nf], a[mf], b);
            }
        }
        __syncthreads();   // protect stage `it` from next iteration's prefetch
    }

    // ---- epilogue 1: H' = tf32(gelu(H)*mask), pair-permuted into SMEM ----
    {
        const int i0 = 2*t4, i1 = 2*t4 + 1;
        const int p0 = perm8(i0), p1 = perm8(i1);
        #pragma unroll
        for (int mf = 0; mf < 2; mf++){
            int r0 = mw*32 + mf*16 + g;
            float m[2][2];   // [row 0/8][ex half of warp N-tile]
            #pragma unroll
            for (int h = 0; h < 2; h++){
                int ex = 2*nw + h;
                m[0][h] = g_mask[(tokBase + r0    )*8 + ex];
                m[1][h] = g_mask[(tokBase + r0 + 8)*8 + ex];
            }
            #pragma unroll
            for (int nf = 0; nf < 4; nf++){
                int cb = nw*32 + nf*8;
                float m0 = m[0][nf >> 1], m1 = m[1][nf >> 1];
                Hs[r0*PAD2 + cb + p0]     = rndtf(gelu_exact(acc[mf][nf][0]) * m0);
                Hs[r0*PAD2 + cb + p1]     = rndtf(gelu_exact(acc[mf][nf][1]) * m0);
                Hs[(r0+8)*PAD2 + cb + p0] = rndtf(gelu_exact(acc[mf][nf][2]) * m1);
                Hs[(r0+8)*PAD2 + cb + p1] = rndtf(gelu_exact(acc[mf][nf][3]) * m1);
            }
        }
    }
    __syncthreads();   // Hs complete; X/W region now reusable as Bs2

    // ------------- GEMM2: out = H' @ B2^T, 32 chunks of 64 dims -------------
    auto loadB = [&](int n2){
        int buf = n2 & 1;
        int dBase = n2 * 64;
        #pragma unroll
        for (int i = 0; i < 4; i++){
            int q = tid + i*512; int row = q >> 5; int c4 = q & 31;
            cp16(&Bs2[buf*64*PAD2 + row*PAD2 + c4*4],
                 &g_B2[(size_t)(dBase + row)*NFEAT + c4*4]);
        }
    };

    loadB(0); cp_commit();

    for (int n2 = 0; n2 < 32; n2++){
        if (n2 + 1 < 32){ loadB(n2 + 1); cp_commit(); cp_wait<1>(); }
        else            { cp_wait<0>(); }
        __syncthreads();   // publish chunk n2

        float acc2[2][2][4];
        #pragma unroll
        for (int mf = 0; mf < 2; mf++)
            #pragma unroll
            for (int nf = 0; nf < 2; nf++)
                #pragma unroll
                for (int k = 0; k < 4; k++) acc2[mf][nf][k] = 0.f;

        const float* Hb = Hs + mw*32*PAD2;
        const float* Bb = Bs2 + (n2 & 1)*64*PAD2 + nw*16*PAD2;
        #pragma unroll
        for (int ks = 0; ks < 16; ks++){
            int kc = ks * 8;
            uint32_t a[2][4];
            #pragma unroll
            for (int mf = 0; mf < 2; mf++){
                float2 v0 = *reinterpret_cast<const float2*>(
                    &Hb[(mf*16 +     g)*PAD2 + kc + 2*t4]);
                float2 v1 = *reinterpret_cast<const float2*>(
                    &Hb[(mf*16 + 8 + g)*PAD2 + kc + 2*t4]);
                a[mf][0] = __float_as_uint(v0.x);
                a[mf][1] = __float_as_uint(v1.x);
                a[mf][2] = __float_as_uint(v0.y);
                a[mf][3] = __float_as_uint(v1.y);
            }
            #pragma unroll
            for (int nf = 0; nf < 2; nf++){
                float2 bv = *reinterpret_cast<const float2*>(
                    &Bb[(nf*8 + g)*PAD2 + kc + 2*t4]);
                uint32_t b[2] = { __float_as_uint(bv.x), __float_as_uint(bv.y) };
                #pragma unroll
                for (int mf = 0; mf < 2; mf++) mma8(acc2[mf][nf], a[mf], b);
            }
        }

        int dBase = n2 * 64;
        #pragma unroll
        for (int mf = 0; mf < 2; mf++){
            int r0 = tokBase + mw*32 + mf*16 + g;
            #pragma unroll
            for (int nf = 0; nf < 2; nf++){
                int c0 = dBase + nw*16 + nf*8 + 2*t4;
                *reinterpret_cast<float2*>(&out[(size_t)r0*DIM + c0]) =
                    make_float2(acc2[mf][nf][0], acc2[mf][nf][1]);
                *reinterpret_cast<float2*>(&out[(size_t)(r0+8)*DIM + c0]) =
                    make_float2(acc2[mf][nf][2], acc2[mf][nf][3]);
            }
        }
        __syncthreads();   // protect buffer (n2&1) from next prefetch
    }
}

// ============================ launch ============================
extern "C" void kernel_launch(void* const* d_in, const int* in_sizes, int n_in,
                              void* d_out, int out_size)
{
    const float* x  = (const float*)d_in[0];
    const float* gW = (const float*)d_in[1];
    const float* gb = (const float*)d_in[2];
    const float* A  = (const float*)d_in[3];   // [8,16,2048] == W1 [128,2048]
    const float* Bm = (const float*)d_in[4];   // [8,2048,16]

    float* out = (float*)d_out;
    float* probs = out + (size_t)TOKENS * DIM;
    if (out_size < TOKENS*DIM + TOKENS*NEXP){
        void* p = nullptr;
        cudaGetSymbolAddress(&p, g_probs_fallback);
        probs = (float*)p;
    }

    size_t gate_smem  = (size_t)NEXP * DIM * sizeof(float);                    // 64KB
    size_t fused_smem = (size_t)(6*SA_STAGE + 128*PAD2) * sizeof(float);       // 178KB
    cudaFuncSetAttribute(gate_kernel, cudaFuncAttributeMaxDynamicSharedMemorySize,
                         (int)gate_smem);
    cudaFuncSetAttribute(fused_kernel, cudaFuncAttributeMaxDynamicSharedMemorySize,
                         (int)fused_smem);

    gate_kernel<<<256, 512, gate_smem>>>(x, gW, gb, probs);
    pack_kernel<<<(2*DIM*NFEAT + 511)/512, 512>>>(Bm, A);
    fused_kernel<<<128, 512, fused_smem>>>(x, out);
}

// round 11
// speedup vs baseline: 1.7228x; 1.7228x over previous
#include <cuda_runtime.h>
#include <cstdint>
#include <math.h>

#define TOKENS 16384
#define DIM    2048
#define NEXP   8
#define RANK   16
#define NFEAT  128
#define NTMAX  192           // max tiles: 128 full + 27 ragged < 192
#define PAD    36            // 36%32==4 -> conflict-free; 36*4=144 = 9*16B aligned
#define XSTG   (128*PAD)     // X stage floats
#define WSTG   (32*PAD)      // W stage floats

// -------- device scratch --------
__device__ float g_W1c[NFEAT*DIM];        // rna-tf32 pre-rounded A  [128,2048]
__device__ float g_B2[NEXP*DIM*RANK];     // rna-tf32 pre-rounded Bm [8,2048,16]
__device__ int   g_pid[TOKENS];
__device__ int   g_cnt[64], g_off[64], g_pos[64];
__device__ int   g_idx[TOKENS];
__device__ int   g_tilepid[NTMAX], g_tilestart[NTMAX], g_tilelen[NTMAX];
__device__ float g_probs_fallback[TOKENS*NEXP];

// -------- helpers --------
__device__ __forceinline__ uint32_t f2tf(float f){
    uint32_t u; asm("cvt.rna.tf32.f32 %0, %1;" : "=r"(u) : "f"(f)); return u;
}
__device__ __forceinline__ float rndtf(float f){ return __uint_as_float(f2tf(f)); }
__device__ __forceinline__ void mma8(float c[4], const uint32_t a[4], const uint32_t b[2]){
    asm volatile(
      "mma.sync.aligned.m16n8k8.row.col.f32.tf32.tf32.f32 "
      "{%0,%1,%2,%3},{%4,%5,%6,%7},{%8,%9},{%0,%1,%2,%3};"
      : "+f"(c[0]), "+f"(c[1]), "+f"(c[2]), "+f"(c[3])
      : "r"(a[0]), "r"(a[1]), "r"(a[2]), "r"(a[3]), "r"(b[0]), "r"(b[1]));
}
__device__ __forceinline__ void cp16(void* s, const void* g){
    uint32_t sa = (uint32_t)__cvta_generic_to_shared(s);
    asm volatile("cp.async.cg.shared.global [%0], [%1], 16;" :: "r"(sa), "l"(g));
}
__device__ __forceinline__ void cp_commit(){ asm volatile("cp.async.commit_group;"); }
template<int N> __device__ __forceinline__ void cp_wait(){
    asm volatile("cp.async.wait_group %0;" :: "n"(N));
}
__device__ __forceinline__ float gelu_exact(float v){
    return 0.5f * v * (1.0f + erff(v * 0.70710678118654752f));
}

// ================= Kernel 0: zero counters =================
__global__ void zero_kernel(){
    int t = threadIdx.x;
    if (t < 64){ g_cnt[t] = 0; g_pos[t] = 0; }
}

// ================= Kernel 1: gate (fp32 exact) + pair histogram =================
// 512 thr, 4 tokens/warp -> 64 tokens/CTA, grid 256. W staged in SMEM.
__global__ __launch_bounds__(512) void gate_kernel(
    const float* __restrict__ x, const float* __restrict__ W,
    const float* __restrict__ bias, float* __restrict__ probs)
{
    extern __shared__ float Wsm[];
    {
        const float4* Wg = reinterpret_cast<const float4*>(W);
        float4* Ws4 = reinterpret_cast<float4*>(Wsm);
        for (int i = threadIdx.x; i < NEXP*DIM/4; i += 512) Ws4[i] = Wg[i];
    }
    __syncthreads();
    int warp = threadIdx.x >> 5, lane = threadIdx.x & 31;
    int tok0 = (blockIdx.x * 16 + warp) * 4;
    const float4* x4 = reinterpret_cast<const float4*>(x);
    const float4* W4 = reinterpret_cast<const float4*>(Wsm);
    float acc[4][8];
    #pragma unroll
    for (int t = 0; t < 4; t++)
        #pragma unroll
        for (int e = 0; e < 8; e++) acc[t][e] = 0.f;
    #pragma unroll 2
    for (int i = lane; i < 512; i += 32){
        float4 xv[4];
        #pragma unroll
        for (int t = 0; t < 4; t++) xv[t] = x4[(size_t)(tok0 + t) * 512 + i];
        #pragma unroll
        for (int e = 0; e < 8; e++){
            float4 w = W4[e * 512 + i];
            #pragma unroll
            for (int t = 0; t < 4; t++)
                acc[t][e] += xv[t].x*w.x + xv[t].y*w.y + xv[t].z*w.z + xv[t].w*w.w;
        }
    }
    #pragma unroll
    for (int t = 0; t < 4; t++)
        #pragma unroll
        for (int e = 0; e < 8; e++){
            float v = acc[t][e];
            #pragma unroll
            for (int s = 16; s > 0; s >>= 1) v += __shfl_xor_sync(0xffffffffu, v, s);
            acc[t][e] = v;
        }
    if (lane < 4){
        int t = lane, tok = tok0 + t;
        float lg[8]; float mx = -1e30f;
        #pragma unroll
        for (int e = 0; e < 8; e++){ lg[e] = acc[t][e] + bias[e]; mx = fmaxf(mx, lg[e]); }
        float p[8]; float s = 0.f;
        #pragma unroll
        for (int e = 0; e < 8; e++){ p[e] = expf(lg[e] - mx); s += p[e]; }
        float inv = 1.f / s;
        #pragma unroll
        for (int e = 0; e < 8; e++) probs[tok*8 + e] = p[e] * inv;
        // top-2 (lowest index wins ties, matching jax top_k)
        int i1 = 0;
        #pragma unroll
        for (int e = 1; e < 8; e++) if (lg[e] > lg[i1]) i1 = e;
        int i2 = (i1 == 0) ? 1 : 0;
        #pragma unroll
        for (int e = 0; e < 8; e++) if (e != i1 && lg[e] > lg[i2]) i2 = e;
        int lo = min(i1, i2), hi = max(i1, i2);
        int pid = lo*8 + hi;
        g_pid[tok] = pid;
        atomicAdd(&g_cnt[pid], 1);
    }
}

// ================= Kernel 2: scan + tile list =================
__global__ void scan_kernel(){
    if (threadIdx.x == 0 && blockIdx.x == 0){
        int off = 0;
        for (int b = 0; b < 64; b++){ g_off[b] = off; off += g_cnt[b]; }
        int t = 0;
        for (int b = 0; b < 64; b++){
            int c = g_cnt[b], s = g_off[b];
            while (c > 0){
                g_tilepid[t] = b; g_tilestart[t] = s;
                g_tilelen[t] = (c < 128) ? c : 128;
                s += 128; c -= 128; t++;
            }
        }
        for (; t < NTMAX; t++) g_tilelen[t] = 0;
    }
}

// ================= Kernel 3: fill sorted index =================
__global__ void fill_kernel(){
    int tok = blockIdx.x * blockDim.x + threadIdx.x;
    if (tok < TOKENS){
        int pid = g_pid[tok];
        int slot = g_off[pid] + atomicAdd(&g_pos[pid], 1);
        g_idx[slot] = tok;
    }
}

// ================= Kernel 4: pre-round weights (elementwise) =================
__global__ void pack_kernel(const float* __restrict__ Bm, const float* __restrict__ A){
    int t = blockIdx.x * blockDim.x + threadIdx.x;
    if (t < NFEAT * DIM)          g_W1c[t] = rndtf(A[t]);
    else if (t < 2 * NFEAT * DIM) g_B2[t - NFEAT*DIM] = rndtf(Bm[t - NFEAT*DIM]);
}

// ========= Kernel 5: sparse fused GEMM1(K=2048,N=32) -> gelu -> GEMM2(K=32) =========
// one tile (<=128 tokens of one expert pair) per CTA. 256 thr, 8 warps (4M x 2N).
__global__ __launch_bounds__(256, 2) void fused_kernel(
    const float* __restrict__ x, float* __restrict__ out)
{
    const int len = g_tilelen[blockIdx.x];
    if (len == 0) return;
    const int start = g_tilestart[blockIdx.x];
    const int pid   = g_tilepid[blockIdx.x];
    const int e1 = pid >> 3, e2 = pid & 7;

    extern __shared__ float sm[];
    float* Xs  = sm;                       // 3 * 4608
    float* Ws  = Xs + 3*XSTG;              // 3 * 1152
    float* Hs  = Ws + 3*WSTG;              // 4608
    float* Bs  = Hs + 128*PAD;             // 2 * 2304
    int*   idx = reinterpret_cast<int*>(Bs + 2*64*PAD);   // 128

    const int tid  = threadIdx.x;
    const int warp = tid >> 5, lane = tid & 31;
    const int g = lane >> 2, t4 = lane & 3;
    const int mw = warp & 3, nw = warp >> 2;

    if (tid < 128){
        int r = (tid < len) ? tid : (len - 1);
        idx[tid] = g_idx[start + r];
    }
    __syncthreads();

    // ---------------- GEMM1: H = Xg @ Wslice^T, K = 2048, 3-stage PF=2 ----------------
    float acc[2][2][4];
    #pragma unroll
    for (int mf = 0; mf < 2; mf++)
        #pragma unroll
        for (int nf = 0; nf < 2; nf++)
            #pragma unroll
            for (int k = 0; k < 4; k++) acc[mf][nf][k] = 0.f;

    // this thread's W-slice row (f = tid>>3): global feature row in g_W1c
    const int wf  = tid >> 3;
    const int gf  = (wf < 16) ? (e1*16 + wf) : (e2*16 + wf - 16);
    const int wc4 = tid & 7;
    const float* wsrc = g_W1c + (size_t)gf * DIM + wc4*4;

    auto loadStage = [&](int s){
        int st = (s % 3);
        int kb = s * 32;
        #pragma unroll
        for (int i = 0; i < 4; i++){
            int q = tid + i*256; int row = q >> 3; int c4 = q & 7;
            cp16(&Xs[st*XSTG + row*PAD + c4*4],
                 x + (size_t)idx[row]*DIM + kb + c4*4);
        }
        cp16(&Ws[st*WSTG + wf*PAD + wc4*4], wsrc + kb);
        cp_commit();
    };

    loadStage(0); loadStage(1);

    for (int s = 0; s < 64; s++){
        if (s + 2 < 64) loadStage(s + 2);
        if      (s + 2 < 64) cp_wait<2>();
        else if (s + 1 < 64) cp_wait<1>();
        else                 cp_wait<0>();
        __syncthreads();

        const float* Ab = Xs + (s % 3)*XSTG + mw*32*PAD;
        const float* Wb = Ws + (s % 3)*WSTG + nw*16*PAD;
        #pragma unroll
        for (int ks = 0; ks < 4; ks++){
            int kc = ks * 8;
            uint32_t a[2][4];
            #pragma unroll
            for (int mf = 0; mf < 2; mf++){
                a[mf][0] = f2tf(Ab[(mf*16 +     g)*PAD + kc + t4]);
                a[mf][1] = f2tf(Ab[(mf*16 + 8 + g)*PAD + kc + t4]);
                a[mf][2] = f2tf(Ab[(mf*16 +     g)*PAD + kc + t4 + 4]);
                a[mf][3] = f2tf(Ab[(mf*16 + 8 + g)*PAD + kc + t4 + 4]);
            }
            #pragma unroll
            for (int nf = 0; nf < 2; nf++){
                uint32_t b[2];
                b[0] = __float_as_uint(Wb[(nf*8 + g)*PAD + kc + t4]);
                b[1] = __float_as_uint(Wb[(nf*8 + g)*PAD + kc + t4 + 4]);
                #pragma unroll
                for (int mf = 0; mf < 2; mf++) mma8(acc[mf][nf], a[mf], b);
            }
        }
        __syncthreads();
    }

    // ---- epilogue 1: H' = tf32(gelu(H)) -> Hs (mask implicit: pair is top-2) ----
    #pragma unroll
    for (int mf = 0; mf < 2; mf++){
        int r0 = mw*32 + mf*16 + g;
        #pragma unroll
        for (int nf = 0; nf < 2; nf++){
            int c0 = nw*16 + nf*8 + 2*t4;
            Hs[r0*PAD + c0]       = rndtf(gelu_exact(acc[mf][nf][0]));
            Hs[r0*PAD + c0 + 1]   = rndtf(gelu_exact(acc[mf][nf][1]));
            Hs[(r0+8)*PAD + c0]   = rndtf(gelu_exact(acc[mf][nf][2]));
            Hs[(r0+8)*PAD + c0+1] = rndtf(gelu_exact(acc[mf][nf][3]));
        }
    }
    __syncthreads();

    // ------ GEMM2: out = H' @ [B_e1;B_e2]^T, K = 32, 32 chunks of 64 dims ------
    auto loadB = [&](int c){
        int buf = c & 1;
        int dBase = c * 64;
        #pragma unroll
        for (int i = 0; i < 2; i++){
            int q = tid + i*256;            // 0..511
            int d = q >> 3; int j4 = q & 7; // d 0..63, 8 chunks of 4 feats
            const float* src = (j4 < 4)
                ? g_B2 + ((size_t)e1*DIM + dBase + d)*RANK + j4*4
                : g_B2 + ((size_t)e2*DIM + dBase + d)*RANK + (j4-4)*4;
            cp16(&Bs[buf*64*PAD + d*PAD + j4*4], src);
        }
        cp_commit();
    };

    loadB(0);

    for (int c = 0; c < 32; c++){
        if (c + 1 < 32){ loadB(c + 1); cp_wait<1>(); }
        else           { cp_wait<0>(); }
        __syncthreads();

        float acc2[2][4][4];
        #pragma unroll
        for (int mf = 0; mf < 2; mf++)
            #pragma unroll
            for (int nf = 0; nf < 4; nf++)
                #pragma unroll
                for (int k = 0; k < 4; k++) acc2[mf][nf][k] = 0.f;

        const float* Hb = Hs + mw*32*PAD;
        const float* Bb = Bs + (c & 1)*64*PAD + nw*32*PAD;
        #pragma unroll
        for (int ks = 0; ks < 4; ks++){
            int kc = ks * 8;
            uint32_t a[2][4];
            #pragma unroll
            for (int mf = 0; mf < 2; mf++){
                a[mf][0] = __float_as_uint(Hb[(mf*16 +     g)*PAD + kc + t4]);
                a[mf][1] = __float_as_uint(Hb[(mf*16 + 8 + g)*PAD + kc + t4]);
                a[mf][2] = __float_as_uint(Hb[(mf*16 +     g)*PAD + kc + t4 + 4]);
                a[mf][3] = __float_as_uint(Hb[(mf*16 + 8 + g)*PAD + kc + t4 + 4]);
            }
            #pragma unroll
            for (int nf = 0; nf < 4; nf++){
                uint32_t b[2];
                b[0] = __float_as_uint(Bb[(nf*8 + g)*PAD + kc + t4]);
                b[1] = __float_as_uint(Bb[(nf*8 + g)*PAD + kc + t4 + 4]);
                #pragma unroll
                for (int mf = 0; mf < 2; mf++) mma8(acc2[mf][nf], a[mf], b);
            }
        }

        int dBase = c * 64;
        #pragma unroll
        for (int mf = 0; mf < 2; mf++){
            int ra = mw*32 + mf*16 + g;
            int rb = ra + 8;
            size_t toka = (size_t)idx[ra]*DIM;
            size_t tokb = (size_t)idx[rb]*DIM;
            #pragma unroll
            for (int nf = 0; nf < 4; nf++){
                int c0 = dBase + nw*32 + nf*8 + 2*t4;
                if (ra < len)
                    *reinterpret_cast<float2*>(&out[toka + c0]) =
                        make_float2(acc2[mf][nf][0], acc2[mf][nf][1]);
                if (rb < len)
                    *reinterpret_cast<float2*>(&out[tokb + c0]) =
                        make_float2(acc2[mf][nf][2], acc2[mf][nf][3]);
            }
        }
        __syncthreads();
    }
}

// ============================ launch ============================
extern "C" void kernel_launch(void* const* d_in, const int* in_sizes, int n_in,
                              void* d_out, int out_size)
{
    const float* x  = (const float*)d_in[0];
    const float* gW = (const float*)d_in[1];
    const float* gb = (const float*)d_in[2];
    const float* A  = (const float*)d_in[3];   // [8,16,2048] == W1 [128,2048]
    const float* Bm = (const float*)d_in[4];   // [8,2048,16]

    float* out = (float*)d_out;
    float* probs = out + (size_t)TOKENS * DIM;
    if (out_size < TOKENS*DIM + TOKENS*NEXP){
        void* p = nullptr;
        cudaGetSymbolAddress(&p, g_probs_fallback);
        probs = (float*)p;
    }

    size_t gate_smem  = (size_t)NEXP * DIM * sizeof(float);   // 64KB
    size_t fused_smem = (size_t)(3*XSTG + 3*WSTG + 128*PAD + 2*64*PAD) * sizeof(float)
                      + 128 * sizeof(int);                     // ~106KB
    cudaFuncSetAttribute(gate_kernel, cudaFuncAttributeMaxDynamicSharedMemorySize,
                         (int)gate_smem);
    cudaFuncSetAttribute(fused_kernel, cudaFuncAttributeMaxDynamicSharedMemorySize,
                         (int)fused_smem);

    zero_kernel<<<1, 64>>>();
    gate_kernel<<<256, 512, gate_smem>>>(x, gW, gb, probs);
    scan_kernel<<<1, 32>>>();
    fill_kernel<<<(TOKENS + 255)/256, 256>>>();
    pack_kernel<<<(2*NFEAT*DIM + 511)/512, 512>>>(Bm, A);
    fused_kernel<<<NTMAX, 256, fused_smem>>>(x, out);
}